// round 4
// baseline (speedup 1.0000x reference)
#include <cuda_runtime.h>
#include <cuda_bf16.h>
#include <cstddef>

// Problem constants (fixed by reference: B=8, C=256, H=W=64)
constexpr int B  = 8;
constexpr int C  = 256;
constexpr int OC = 32;
constexpr int N  = 4096;          // H*W
constexpr int ZCH = 16;           // i-chunks for deterministic Z reduction

// ---------------- device scratch (allocation-free rule: __device__ globals) ---
__device__ float g_q [(size_t)B * OC * N];        //   4 MB  [b][d][i]
__device__ float g_k [(size_t)B * OC * N];        //   4 MB  [b][d][j]
__device__ float g_vt[(size_t)B * N  * C];        //  33 MB  [b][i][c]  (V transposed)
__device__ float g_p [(size_t)B * N  * N];        // 536 MB  [b][i][j]  unnormalized exp(S)
__device__ float g_zp[(size_t)B * ZCH * N];       // partial column sums of P
__device__ float g_rz[(size_t)B * N];             // gamma / Z_j

// ---------------- f32x2 packed-FMA helpers (FFMA2, PTX-only path) ------------
__device__ __forceinline__ unsigned long long pack2(float lo, float hi) {
    unsigned long long r;
    asm("mov.b64 %0, {%1, %2};" : "=l"(r) : "f"(lo), "f"(hi));
    return r;
}
__device__ __forceinline__ void fma2(unsigned long long& acc,
                                     unsigned long long a, unsigned long long b) {
    asm("fma.rn.f32x2 %0, %1, %2, %0;" : "+l"(acc) : "l"(a), "l"(b));
}
__device__ __forceinline__ float2 unpack2(unsigned long long v) {
    float lo, hi;
    asm("mov.b64 {%0, %1}, %2;" : "=f"(lo), "=f"(hi) : "l"(v));
    return make_float2(lo, hi);
}

// =============================================================================
// K1: fused QKV projection.  Y[o][n] = sum_c Wcat[o][c] * x[b][c][n]
//     o in [0,320): 0-31 -> q, 32-63 -> k, 64-319 -> v (stored transposed).
//     Block tile 64x64, K-chunk 16, 256 threads, 4x4 micro.
// =============================================================================
__global__ __launch_bounds__(256)
void k1_qkv(const float* __restrict__ x, const float* __restrict__ Wf,
            const float* __restrict__ Wg, const float* __restrict__ Wh) {
    const int b  = blockIdx.z;
    const int o0 = blockIdx.y * 64;
    const int n0 = blockIdx.x * 64;
    __shared__ float Ws[16][68];
    __shared__ float Xs[16][68];
    const int t  = threadIdx.x;
    const int tx = t & 15, ty = t >> 4;

    float acc[4][4] = {};
    const float* xb = x + (size_t)b * C * N;

    for (int kk = 0; kk < C; kk += 16) {
        // W tile (transpose-on-load): Ws[kc][m] = Wcat[o0+m][kk+kc]
        {
            const int m = t >> 2, qd = t & 3;
            const int o = o0 + m;
            const float* src; int oo;
            if (o < 32)      { src = Wf; oo = o; }
            else if (o < 64) { src = Wg; oo = o - 32; }
            else             { src = Wh; oo = o - 64; }
            float4 w4 = *reinterpret_cast<const float4*>(src + (size_t)oo * C + kk + qd * 4);
            Ws[qd * 4 + 0][m] = w4.x; Ws[qd * 4 + 1][m] = w4.y;
            Ws[qd * 4 + 2][m] = w4.z; Ws[qd * 4 + 3][m] = w4.w;
        }
        // X tile: Xs[kc][nn] = x[b][kk+kc][n0+nn]
        {
            const int f = t * 4;
            const int kc = f >> 6, nn = f & 63;
            *reinterpret_cast<float4*>(&Xs[kc][nn]) =
                *reinterpret_cast<const float4*>(xb + (size_t)(kk + kc) * N + n0 + nn);
        }
        __syncthreads();
#pragma unroll
        for (int kc = 0; kc < 16; kc++) {
            float aw[4], bx[4];
#pragma unroll
            for (int i = 0; i < 4; i++) aw[i] = Ws[kc][ty * 4 + i];
#pragma unroll
            for (int j = 0; j < 4; j++) bx[j] = Xs[kc][tx * 4 + j];
#pragma unroll
            for (int i = 0; i < 4; i++)
#pragma unroll
                for (int j = 0; j < 4; j++) acc[i][j] += aw[i] * bx[j];
        }
        __syncthreads();
    }

    if (o0 < 64) {  // q / k rows: store [b][d][n], float4 along n
#pragma unroll
        for (int i = 0; i < 4; i++) {
            const int o = o0 + ty * 4 + i;
            float* dst = (o < 32) ? (g_q + ((size_t)b * OC + o) * N)
                                  : (g_k + ((size_t)b * OC + (o - 32)) * N);
            *reinterpret_cast<float4*>(dst + n0 + tx * 4) =
                make_float4(acc[i][0], acc[i][1], acc[i][2], acc[i][3]);
        }
    } else {        // v rows: store transposed g_vt[b][n][c], float4 along c
        const int c0 = o0 - 64 + ty * 4;
#pragma unroll
        for (int j = 0; j < 4; j++) {
            const int n = n0 + tx * 4 + j;
            *reinterpret_cast<float4*>(g_vt + ((size_t)b * N + n) * C + c0) =
                make_float4(acc[0][j], acc[1][j], acc[2][j], acc[3][j]);
        }
    }
}

// =============================================================================
// K2: S = Q^T K (K-dim = 32), fused exp, store P[b][i][j] = exp(s_ij).
//     Block tile 128x128, 256 threads, 8x8 micro with packed f32x2 FMA.
// =============================================================================
__global__ __launch_bounds__(256)
void k2_scores() {
    const int b  = blockIdx.z;
    const int i0 = blockIdx.y * 128;
    const int j0 = blockIdx.x * 128;
    __shared__ float Qs[32][132];
    __shared__ float Ks[32][132];
    const int t  = threadIdx.x;
    const int tx = t & 15, ty = t >> 4;

    const float* qb = g_q + (size_t)b * OC * N;
    const float* kb = g_k + (size_t)b * OC * N;
#pragma unroll
    for (int s = 0; s < 4; s++) {
        const int f = t * 4 + s * 1024;
        const int d = f >> 7, mm = f & 127;
        *reinterpret_cast<float4*>(&Qs[d][mm]) =
            *reinterpret_cast<const float4*>(qb + (size_t)d * N + i0 + mm);
        *reinterpret_cast<float4*>(&Ks[d][mm]) =
            *reinterpret_cast<const float4*>(kb + (size_t)d * N + j0 + mm);
    }
    __syncthreads();

    unsigned long long acc[8][4];
#pragma unroll
    for (int i = 0; i < 8; i++)
#pragma unroll
        for (int q = 0; q < 4; q++) acc[i][q] = 0ULL;

#pragma unroll
    for (int d = 0; d < 32; d++) {
        const float4 blo = *reinterpret_cast<const float4*>(&Ks[d][tx * 8]);
        const float4 bhi = *reinterpret_cast<const float4*>(&Ks[d][tx * 8 + 4]);
        unsigned long long bb[4] = { pack2(blo.x, blo.y), pack2(blo.z, blo.w),
                                     pack2(bhi.x, bhi.y), pack2(bhi.z, bhi.w) };
        const float4 alo = *reinterpret_cast<const float4*>(&Qs[d][ty * 8]);
        const float4 ahi = *reinterpret_cast<const float4*>(&Qs[d][ty * 8 + 4]);
        const float av[8] = { alo.x, alo.y, alo.z, alo.w, ahi.x, ahi.y, ahi.z, ahi.w };
#pragma unroll
        for (int i = 0; i < 8; i++) {
            const unsigned long long a2 = pack2(av[i], av[i]);
#pragma unroll
            for (int q = 0; q < 4; q++) fma2(acc[i][q], a2, bb[q]);
        }
    }

    float* pb = g_p + (size_t)b * N * N;
#pragma unroll
    for (int i = 0; i < 8; i++) {
        const size_t row = (size_t)(i0 + ty * 8 + i) * N + j0 + tx * 8;
        const float2 v0 = unpack2(acc[i][0]), v1 = unpack2(acc[i][1]);
        const float2 v2 = unpack2(acc[i][2]), v3 = unpack2(acc[i][3]);
        // no max-subtraction needed: |s| <= ~15 comfortably inside fp32 exp range
        *reinterpret_cast<float4*>(pb + row) =
            make_float4(__expf(v0.x), __expf(v0.y), __expf(v1.x), __expf(v1.y));
        *reinterpret_cast<float4*>(pb + row + 4) =
            make_float4(__expf(v2.x), __expf(v2.y), __expf(v3.x), __expf(v3.y));
    }
}

// =============================================================================
// K3a/K3b: deterministic column-sum of P -> Z_j, then rz = gamma / Z.
// =============================================================================
__global__ __launch_bounds__(256)
void k3a_zpart() {
    const int b = blockIdx.z, ic = blockIdx.y;
    const int j = blockIdx.x * 256 + threadIdx.x;
    const float* pb = g_p + (size_t)b * N * N + (size_t)ic * (N / ZCH) * N + j;
    float s = 0.f;
#pragma unroll 8
    for (int i = 0; i < N / ZCH; i++) s += pb[(size_t)i * N];
    g_zp[((size_t)b * ZCH + ic) * N + j] = s;
}

__global__ __launch_bounds__(256)
void k3b_rz(const float* __restrict__ gamma) {
    const int b = blockIdx.y;
    const int j = blockIdx.x * 256 + threadIdx.x;
    float s = 0.f;
#pragma unroll
    for (int ic = 0; ic < ZCH; ic++) s += g_zp[((size_t)b * ZCH + ic) * N + j];
    g_rz[(size_t)b * N + j] = gamma[0] / s;
}

// =============================================================================
// K4: out[b][c][j] = rz[j] * (sum_i V[c][i] * P[i][j]) + x[b][c][j]
//     M=256, N=4096, K=4096 GEMM. Block tile 128x128, K-chunk 16,
//     256 threads, 8x8 micro, packed f32x2 FMA (the 68.7-GFLOP hotspot).
// =============================================================================
__global__ __launch_bounds__(256)
void k4_pv(const float* __restrict__ x, float* __restrict__ out) {
    const int b  = blockIdx.z;
    const int c0 = blockIdx.y * 128;
    const int j0 = blockIdx.x * 128;
    __shared__ float Vs[16][132];
    __shared__ float Ps[16][132];
    const int t  = threadIdx.x;
    const int tx = t & 15, ty = t >> 4;

    unsigned long long acc[8][4];
#pragma unroll
    for (int i = 0; i < 8; i++)
#pragma unroll
        for (int q = 0; q < 4; q++) acc[i][q] = 0ULL;

    const float* vb = g_vt + (size_t)b * N * C;
    const float* pb = g_p  + (size_t)b * N * N;

#pragma unroll 1
    for (int kk = 0; kk < N; kk += 16) {
#pragma unroll
        for (int s = 0; s < 2; s++) {
            const int f = t * 4 + s * 1024;
            const int ki = f >> 7, mm = f & 127;
            *reinterpret_cast<float4*>(&Vs[ki][mm]) =
                *reinterpret_cast<const float4*>(vb + (size_t)(kk + ki) * C + c0 + mm);
            *reinterpret_cast<float4*>(&Ps[ki][mm]) =
                *reinterpret_cast<const float4*>(pb + (size_t)(kk + ki) * N + j0 + mm);
        }
        __syncthreads();
#pragma unroll
        for (int ki = 0; ki < 16; ki++) {
            const float4 blo = *reinterpret_cast<const float4*>(&Ps[ki][tx * 8]);
            const float4 bhi = *reinterpret_cast<const float4*>(&Ps[ki][tx * 8 + 4]);
            unsigned long long bb[4] = { pack2(blo.x, blo.y), pack2(blo.z, blo.w),
                                         pack2(bhi.x, bhi.y), pack2(bhi.z, bhi.w) };
            const float4 alo = *reinterpret_cast<const float4*>(&Vs[ki][ty * 8]);
            const float4 ahi = *reinterpret_cast<const float4*>(&Vs[ki][ty * 8 + 4]);
            const float av[8] = { alo.x, alo.y, alo.z, alo.w, ahi.x, ahi.y, ahi.z, ahi.w };
#pragma unroll
            for (int i = 0; i < 8; i++) {
                const unsigned long long a2 = pack2(av[i], av[i]);
#pragma unroll
                for (int q = 0; q < 4; q++) fma2(acc[i][q], a2, bb[q]);
            }
        }
        __syncthreads();
    }

    // epilogue: scale by gamma/Z, add residual x, write output
    const float* xb = x   + (size_t)b * C * N;
    float*       ob = out + (size_t)b * C * N;
    const float4 rlo = *reinterpret_cast<const float4*>(g_rz + (size_t)b * N + j0 + tx * 8);
    const float4 rhi = *reinterpret_cast<const float4*>(g_rz + (size_t)b * N + j0 + tx * 8 + 4);
    const float rz[8] = { rlo.x, rlo.y, rlo.z, rlo.w, rhi.x, rhi.y, rhi.z, rhi.w };

#pragma unroll
    for (int i = 0; i < 8; i++) {
        const int c = c0 + ty * 8 + i;
        const size_t row = (size_t)c * N + j0 + tx * 8;
        const float4 xlo = *reinterpret_cast<const float4*>(xb + row);
        const float4 xhi = *reinterpret_cast<const float4*>(xb + row + 4);
        const float2 a0 = unpack2(acc[i][0]), a1 = unpack2(acc[i][1]);
        const float2 a2 = unpack2(acc[i][2]), a3 = unpack2(acc[i][3]);
        *reinterpret_cast<float4*>(ob + row) =
            make_float4(fmaf(a0.x, rz[0], xlo.x), fmaf(a0.y, rz[1], xlo.y),
                        fmaf(a1.x, rz[2], xlo.z), fmaf(a1.y, rz[3], xlo.w));
        *reinterpret_cast<float4*>(ob + row + 4) =
            make_float4(fmaf(a2.x, rz[4], xhi.x), fmaf(a2.y, rz[5], xhi.y),
                        fmaf(a3.x, rz[6], xhi.z), fmaf(a3.y, rz[7], xhi.w));
    }
}

// =============================================================================
extern "C" void kernel_launch(void* const* d_in, const int* in_sizes, int n_in,
                              void* d_out, int out_size) {
    const float* x     = (const float*)d_in[0];
    const float* Wf    = (const float*)d_in[1];
    const float* Wg    = (const float*)d_in[2];
    const float* Wh    = (const float*)d_in[3];
    const float* gamma = (const float*)d_in[4];
    float* out = (float*)d_out;

    k1_qkv   <<<dim3(N / 64, 320 / 64, B), 256>>>(x, Wf, Wg, Wh);
    k2_scores<<<dim3(N / 128, N / 128, B), 256>>>();
    k3a_zpart<<<dim3(N / 256, ZCH, B),     256>>>();
    k3b_rz   <<<dim3(N / 256, B),          256>>>(gamma);
    k4_pv    <<<dim3(N / 128, C / 128, B), 256>>>(x, out);
}

// round 5
// speedup vs baseline: 1.0022x; 1.0022x over previous
#include <cuda_runtime.h>
#include <cuda_bf16.h>
#include <cstddef>

// Problem constants (fixed by reference: B=8, C=256, H=W=64)
constexpr int B  = 8;
constexpr int C  = 256;
constexpr int OC = 32;
constexpr int N  = 4096;          // H*W
constexpr int ZCH = 16;           // i-chunks for deterministic Z reduction

// ---------------- device scratch (allocation-free rule: __device__ globals) ---
__device__ float g_q [(size_t)B * OC * N];        //   4 MB  [b][d][i]
__device__ float g_k [(size_t)B * OC * N];        //   4 MB  [b][d][j]
__device__ float g_vt[(size_t)B * N  * C];        //  33 MB  [b][i][c]  (V transposed)
__device__ float g_p [(size_t)B * N  * N];        // 536 MB  [b][i][j]  unnormalized exp(S)
__device__ float g_zp[(size_t)B * ZCH * N];       // partial column sums of P
__device__ float g_rz[(size_t)B * N];             // gamma / Z_j

// ---------------- f32x2 packed-FMA helpers (FFMA2, PTX-only path) ------------
__device__ __forceinline__ unsigned long long pack2(float lo, float hi) {
    unsigned long long r;
    asm("mov.b64 %0, {%1, %2};" : "=l"(r) : "f"(lo), "f"(hi));
    return r;
}
__device__ __forceinline__ void fma2(unsigned long long& acc,
                                     unsigned long long a, unsigned long long b) {
    asm("fma.rn.f32x2 %0, %1, %2, %0;" : "+l"(acc) : "l"(a), "l"(b));
}
__device__ __forceinline__ float2 unpack2(unsigned long long v) {
    float lo, hi;
    asm("mov.b64 {%0, %1}, %2;" : "=f"(lo), "=f"(hi) : "l"(v));
    return make_float2(lo, hi);
}

// =============================================================================
// K1: fused QKV projection.  Y[o][n] = sum_c Wcat[o][c] * x[b][c][n]
//     o in [0,320): 0-31 -> q, 32-63 -> k, 64-319 -> v (stored transposed).
//     Block tile 64x64, K-chunk 16, 256 threads, 4x4 micro.
// =============================================================================
__global__ __launch_bounds__(256)
void k1_qkv(const float* __restrict__ x, const float* __restrict__ Wf,
            const float* __restrict__ Wg, const float* __restrict__ Wh) {
    const int b  = blockIdx.z;
    const int o0 = blockIdx.y * 64;
    const int n0 = blockIdx.x * 64;
    __shared__ float Ws[16][68];
    __shared__ float Xs[16][68];
    const int t  = threadIdx.x;
    const int tx = t & 15, ty = t >> 4;

    float acc[4][4] = {};
    const float* xb = x + (size_t)b * C * N;

    for (int kk = 0; kk < C; kk += 16) {
        // W tile (transpose-on-load): Ws[kc][m] = Wcat[o0+m][kk+kc]
        {
            const int m = t >> 2, qd = t & 3;
            const int o = o0 + m;
            const float* src; int oo;
            if (o < 32)      { src = Wf; oo = o; }
            else if (o < 64) { src = Wg; oo = o - 32; }
            else             { src = Wh; oo = o - 64; }
            float4 w4 = *reinterpret_cast<const float4*>(src + (size_t)oo * C + kk + qd * 4);
            Ws[qd * 4 + 0][m] = w4.x; Ws[qd * 4 + 1][m] = w4.y;
            Ws[qd * 4 + 2][m] = w4.z; Ws[qd * 4 + 3][m] = w4.w;
        }
        // X tile: Xs[kc][nn] = x[b][kk+kc][n0+nn]
        {
            const int f = t * 4;
            const int kc = f >> 6, nn = f & 63;
            *reinterpret_cast<float4*>(&Xs[kc][nn]) =
                *reinterpret_cast<const float4*>(xb + (size_t)(kk + kc) * N + n0 + nn);
        }
        __syncthreads();
#pragma unroll
        for (int kc = 0; kc < 16; kc++) {
            float aw[4], bx[4];
#pragma unroll
            for (int i = 0; i < 4; i++) aw[i] = Ws[kc][ty * 4 + i];
#pragma unroll
            for (int j = 0; j < 4; j++) bx[j] = Xs[kc][tx * 4 + j];
#pragma unroll
            for (int i = 0; i < 4; i++)
#pragma unroll
                for (int j = 0; j < 4; j++) acc[i][j] += aw[i] * bx[j];
        }
        __syncthreads();
    }

    if (o0 < 64) {  // q / k rows: store [b][d][n], float4 along n
#pragma unroll
        for (int i = 0; i < 4; i++) {
            const int o = o0 + ty * 4 + i;
            float* dst = (o < 32) ? (g_q + ((size_t)b * OC + o) * N)
                                  : (g_k + ((size_t)b * OC + (o - 32)) * N);
            *reinterpret_cast<float4*>(dst + n0 + tx * 4) =
                make_float4(acc[i][0], acc[i][1], acc[i][2], acc[i][3]);
        }
    } else {        // v rows: store transposed g_vt[b][n][c], float4 along c
        const int c0 = o0 - 64 + ty * 4;
#pragma unroll
        for (int j = 0; j < 4; j++) {
            const int n = n0 + tx * 4 + j;
            *reinterpret_cast<float4*>(g_vt + ((size_t)b * N + n) * C + c0) =
                make_float4(acc[0][j], acc[1][j], acc[2][j], acc[3][j]);
        }
    }
}

// =============================================================================
// K2: S = Q^T K (K-dim = 32), fused exp, store P[b][i][j] = exp(s_ij).
//     Block tile 128x128, 256 threads, 8x8 micro with packed f32x2 FMA.
// =============================================================================
__global__ __launch_bounds__(256)
void k2_scores() {
    const int b  = blockIdx.z;
    const int i0 = blockIdx.y * 128;
    const int j0 = blockIdx.x * 128;
    __shared__ float Qs[32][132];
    __shared__ float Ks[32][132];
    const int t  = threadIdx.x;
    const int tx = t & 15, ty = t >> 4;

    const float* qb = g_q + (size_t)b * OC * N;
    const float* kb = g_k + (size_t)b * OC * N;
#pragma unroll
    for (int s = 0; s < 4; s++) {
        const int f = t * 4 + s * 1024;
        const int d = f >> 7, mm = f & 127;
        *reinterpret_cast<float4*>(&Qs[d][mm]) =
            *reinterpret_cast<const float4*>(qb + (size_t)d * N + i0 + mm);
        *reinterpret_cast<float4*>(&Ks[d][mm]) =
            *reinterpret_cast<const float4*>(kb + (size_t)d * N + j0 + mm);
    }
    __syncthreads();

    unsigned long long acc[8][4];
#pragma unroll
    for (int i = 0; i < 8; i++)
#pragma unroll
        for (int q = 0; q < 4; q++) acc[i][q] = 0ULL;

#pragma unroll
    for (int d = 0; d < 32; d++) {
        const float4 blo = *reinterpret_cast<const float4*>(&Ks[d][tx * 8]);
        const float4 bhi = *reinterpret_cast<const float4*>(&Ks[d][tx * 8 + 4]);
        unsigned long long bb[4] = { pack2(blo.x, blo.y), pack2(blo.z, blo.w),
                                     pack2(bhi.x, bhi.y), pack2(bhi.z, bhi.w) };
        const float4 alo = *reinterpret_cast<const float4*>(&Qs[d][ty * 8]);
        const float4 ahi = *reinterpret_cast<const float4*>(&Qs[d][ty * 8 + 4]);
        const float av[8] = { alo.x, alo.y, alo.z, alo.w, ahi.x, ahi.y, ahi.z, ahi.w };
#pragma unroll
        for (int i = 0; i < 8; i++) {
            const unsigned long long a2 = pack2(av[i], av[i]);
#pragma unroll
            for (int q = 0; q < 4; q++) fma2(acc[i][q], a2, bb[q]);
        }
    }

    float* pb = g_p + (size_t)b * N * N;
#pragma unroll
    for (int i = 0; i < 8; i++) {
        const size_t row = (size_t)(i0 + ty * 8 + i) * N + j0 + tx * 8;
        const float2 v0 = unpack2(acc[i][0]), v1 = unpack2(acc[i][1]);
        const float2 v2 = unpack2(acc[i][2]), v3 = unpack2(acc[i][3]);
        // no max-subtraction needed: |s| <= ~15 comfortably inside fp32 exp range
        *reinterpret_cast<float4*>(pb + row) =
            make_float4(__expf(v0.x), __expf(v0.y), __expf(v1.x), __expf(v1.y));
        *reinterpret_cast<float4*>(pb + row + 4) =
            make_float4(__expf(v2.x), __expf(v2.y), __expf(v3.x), __expf(v3.y));
    }
}

// =============================================================================
// K3a/K3b: deterministic column-sum of P -> Z_j, then rz = gamma / Z.
// =============================================================================
__global__ __launch_bounds__(256)
void k3a_zpart() {
    const int b = blockIdx.z, ic = blockIdx.y;
    const int j = blockIdx.x * 256 + threadIdx.x;
    const float* pb = g_p + (size_t)b * N * N + (size_t)ic * (N / ZCH) * N + j;
    float s = 0.f;
#pragma unroll 8
    for (int i = 0; i < N / ZCH; i++) s += pb[(size_t)i * N];
    g_zp[((size_t)b * ZCH + ic) * N + j] = s;
}

__global__ __launch_bounds__(256)
void k3b_rz(const float* __restrict__ gamma) {
    const int b = blockIdx.y;
    const int j = blockIdx.x * 256 + threadIdx.x;
    float s = 0.f;
#pragma unroll
    for (int ic = 0; ic < ZCH; ic++) s += g_zp[((size_t)b * ZCH + ic) * N + j];
    g_rz[(size_t)b * N + j] = gamma[0] / s;
}

// =============================================================================
// K4: out[b][c][j] = rz[j] * (sum_i V[c][i] * P[i][j]) + x[b][c][j]
//     M=256, N=4096, K=4096 GEMM. Block tile 128x128, K-chunk 16,
//     256 threads, 8x8 micro, packed f32x2 FMA (the 68.7-GFLOP hotspot).
// =============================================================================
__global__ __launch_bounds__(256)
void k4_pv(const float* __restrict__ x, float* __restrict__ out) {
    const int b  = blockIdx.z;
    const int c0 = blockIdx.y * 128;
    const int j0 = blockIdx.x * 128;
    __shared__ float Vs[16][132];
    __shared__ float Ps[16][132];
    const int t  = threadIdx.x;
    const int tx = t & 15, ty = t >> 4;

    unsigned long long acc[8][4];
#pragma unroll
    for (int i = 0; i < 8; i++)
#pragma unroll
        for (int q = 0; q < 4; q++) acc[i][q] = 0ULL;

    const float* vb = g_vt + (size_t)b * N * C;
    const float* pb = g_p  + (size_t)b * N * N;

#pragma unroll 1
    for (int kk = 0; kk < N; kk += 16) {
#pragma unroll
        for (int s = 0; s < 2; s++) {
            const int f = t * 4 + s * 1024;
            const int ki = f >> 7, mm = f & 127;
            *reinterpret_cast<float4*>(&Vs[ki][mm]) =
                *reinterpret_cast<const float4*>(vb + (size_t)(kk + ki) * C + c0 + mm);
            *reinterpret_cast<float4*>(&Ps[ki][mm]) =
                *reinterpret_cast<const float4*>(pb + (size_t)(kk + ki) * N + j0 + mm);
        }
        __syncthreads();
#pragma unroll
        for (int ki = 0; ki < 16; ki++) {
            const float4 blo = *reinterpret_cast<const float4*>(&Ps[ki][tx * 8]);
            const float4 bhi = *reinterpret_cast<const float4*>(&Ps[ki][tx * 8 + 4]);
            unsigned long long bb[4] = { pack2(blo.x, blo.y), pack2(blo.z, blo.w),
                                         pack2(bhi.x, bhi.y), pack2(bhi.z, bhi.w) };
            const float4 alo = *reinterpret_cast<const float4*>(&Vs[ki][ty * 8]);
            const float4 ahi = *reinterpret_cast<const float4*>(&Vs[ki][ty * 8 + 4]);
            const float av[8] = { alo.x, alo.y, alo.z, alo.w, ahi.x, ahi.y, ahi.z, ahi.w };
#pragma unroll
            for (int i = 0; i < 8; i++) {
                const unsigned long long a2 = pack2(av[i], av[i]);
#pragma unroll
                for (int q = 0; q < 4; q++) fma2(acc[i][q], a2, bb[q]);
            }
        }
        __syncthreads();
    }

    // epilogue: scale by gamma/Z, add residual x, write output
    const float* xb = x   + (size_t)b * C * N;
    float*       ob = out + (size_t)b * C * N;
    const float4 rlo = *reinterpret_cast<const float4*>(g_rz + (size_t)b * N + j0 + tx * 8);
    const float4 rhi = *reinterpret_cast<const float4*>(g_rz + (size_t)b * N + j0 + tx * 8 + 4);
    const float rz[8] = { rlo.x, rlo.y, rlo.z, rlo.w, rhi.x, rhi.y, rhi.z, rhi.w };

#pragma unroll
    for (int i = 0; i < 8; i++) {
        const int c = c0 + ty * 8 + i;
        const size_t row = (size_t)c * N + j0 + tx * 8;
        const float4 xlo = *reinterpret_cast<const float4*>(xb + row);
        const float4 xhi = *reinterpret_cast<const float4*>(xb + row + 4);
        const float2 a0 = unpack2(acc[i][0]), a1 = unpack2(acc[i][1]);
        const float2 a2 = unpack2(acc[i][2]), a3 = unpack2(acc[i][3]);
        *reinterpret_cast<float4*>(ob + row) =
            make_float4(fmaf(a0.x, rz[0], xlo.x), fmaf(a0.y, rz[1], xlo.y),
                        fmaf(a1.x, rz[2], xlo.z), fmaf(a1.y, rz[3], xlo.w));
        *reinterpret_cast<float4*>(ob + row + 4) =
            make_float4(fmaf(a2.x, rz[4], xhi.x), fmaf(a2.y, rz[5], xhi.y),
                        fmaf(a3.x, rz[6], xhi.z), fmaf(a3.y, rz[7], xhi.w));
    }
}

// =============================================================================
extern "C" void kernel_launch(void* const* d_in, const int* in_sizes, int n_in,
                              void* d_out, int out_size) {
    const float* x     = (const float*)d_in[0];
    const float* Wf    = (const float*)d_in[1];
    const float* Wg    = (const float*)d_in[2];
    const float* Wh    = (const float*)d_in[3];
    const float* gamma = (const float*)d_in[4];
    float* out = (float*)d_out;

    k1_qkv   <<<dim3(N / 64, 320 / 64, B), 256>>>(x, Wf, Wg, Wh);
    k2_scores<<<dim3(N / 128, N / 128, B), 256>>>();
    k3a_zpart<<<dim3(N / 256, ZCH, B),     256>>>();
    k3b_rz   <<<dim3(N / 256, B),          256>>>(gamma);
    k4_pv    <<<dim3(N / 128, C / 128, B), 256>>>(x, out);
}

// round 11
// speedup vs baseline: 4.3176x; 4.3082x over previous
#include <cuda_runtime.h>
#include <cuda_bf16.h>
#include <cstdint>
#include <cstddef>

constexpr int B  = 8;
constexpr int C  = 256;
constexpr int OC = 32;
constexpr int N  = 4096;

// ---------------- device scratch (allocation-free rule) ----------------------
__device__ float         g_q [(size_t)B * OC * N];   // [b][d][i] fp32
__device__ float         g_k [(size_t)B * OC * N];   // [b][d][j] fp32
__device__ __nv_bfloat16 g_v [(size_t)B * C * N];    // [b][c][i] bf16 (GEMM A)
__device__ __nv_bfloat16 g_pt[(size_t)B * N * N];    // [b][j][i] = exp(s_ij) bf16 (GEMM B)
__device__ float         g_rz[(size_t)B * N];        // gamma / Z_j

// ---------------- PTX helpers ------------------------------------------------
__device__ __forceinline__ uint32_t smem_u32(const void* p) {
    uint32_t a;
    asm("{ .reg .u64 t; cvta.to.shared.u64 t, %1; cvt.u32.u64 %0, t; }" : "=r"(a) : "l"(p));
    return a;
}
__device__ __forceinline__ uint32_t sw128(uint32_t o) { return o ^ ((o >> 3) & 0x70); }
__device__ __forceinline__ void cp16(uint32_t s, const void* g) {
    asm volatile("cp.async.cg.shared.global [%0], [%1], 16;" :: "r"(s), "l"(g));
}
__device__ __forceinline__ void cp_commit() { asm volatile("cp.async.commit_group;"); }
template <int G> __device__ __forceinline__ void cp_wait() {
    asm volatile("cp.async.wait_group %0;" :: "n"(G));
}
__device__ __forceinline__ void ldsm4(uint32_t& r0, uint32_t& r1, uint32_t& r2, uint32_t& r3,
                                      uint32_t a) {
    asm volatile("ldmatrix.sync.aligned.m8n8.x4.shared.b16 {%0,%1,%2,%3}, [%4];"
                 : "=r"(r0), "=r"(r1), "=r"(r2), "=r"(r3) : "r"(a));
}
__device__ __forceinline__ void mma16816(float* d, const uint32_t* a, const uint32_t* b) {
    asm volatile("mma.sync.aligned.m16n8k16.row.col.f32.bf16.bf16.f32 "
                 "{%0,%1,%2,%3}, {%4,%5,%6,%7}, {%8,%9}, {%0,%1,%2,%3};"
                 : "+f"(d[0]), "+f"(d[1]), "+f"(d[2]), "+f"(d[3])
                 : "r"(a[0]), "r"(a[1]), "r"(a[2]), "r"(a[3]), "r"(b[0]), "r"(b[1]));
}

// ---------------- f32x2 packed-FMA helpers (K1/K2 SIMT math) -----------------
__device__ __forceinline__ unsigned long long pack2(float lo, float hi) {
    unsigned long long r;
    asm("mov.b64 %0, {%1, %2};" : "=l"(r) : "f"(lo), "f"(hi));
    return r;
}
__device__ __forceinline__ void fma2(unsigned long long& acc,
                                     unsigned long long a, unsigned long long b) {
    asm("fma.rn.f32x2 %0, %1, %2, %0;" : "+l"(acc) : "l"(a), "l"(b));
}
__device__ __forceinline__ float2 unpack2(unsigned long long v) {
    float lo, hi;
    asm("mov.b64 {%0, %1}, %2;" : "=f"(lo), "=f"(hi) : "l"(v));
    return make_float2(lo, hi);
}

// =============================================================================
// K1: QKV projection (fp32 SIMT). q/k -> fp32 [b][d][n]; v -> bf16 [b][c][n].
// =============================================================================
__global__ __launch_bounds__(256)
void k1_qkv(const float* __restrict__ x, const float* __restrict__ Wf,
            const float* __restrict__ Wg, const float* __restrict__ Wh) {
    const int b  = blockIdx.z;
    const int o0 = blockIdx.y * 64;
    const int n0 = blockIdx.x * 64;
    __shared__ float Ws[16][68];
    __shared__ float Xs[16][68];
    const int t = threadIdx.x, tx = t & 15, ty = t >> 4;
    float acc[4][4] = {};
    const float* xb = x + (size_t)b * C * N;

    for (int kk = 0; kk < C; kk += 16) {
        {   // W tile (transpose-on-load)
            const int m = t >> 2, qd = t & 3, o = o0 + m;
            const float* src; int oo;
            if (o < 32)      { src = Wf; oo = o; }
            else if (o < 64) { src = Wg; oo = o - 32; }
            else             { src = Wh; oo = o - 64; }
            float4 w4 = *reinterpret_cast<const float4*>(src + (size_t)oo * C + kk + qd * 4);
            Ws[qd*4+0][m] = w4.x; Ws[qd*4+1][m] = w4.y; Ws[qd*4+2][m] = w4.z; Ws[qd*4+3][m] = w4.w;
        }
        {   // X tile
            const int f = t * 4, kc = f >> 6, nn = f & 63;
            *reinterpret_cast<float4*>(&Xs[kc][nn]) =
                *reinterpret_cast<const float4*>(xb + (size_t)(kk + kc) * N + n0 + nn);
        }
        __syncthreads();
#pragma unroll
        for (int kc = 0; kc < 16; kc++) {
            float aw[4], bx[4];
#pragma unroll
            for (int i = 0; i < 4; i++) aw[i] = Ws[kc][ty*4+i];
#pragma unroll
            for (int j = 0; j < 4; j++) bx[j] = Xs[kc][tx*4+j];
#pragma unroll
            for (int i = 0; i < 4; i++)
#pragma unroll
                for (int j = 0; j < 4; j++) acc[i][j] += aw[i] * bx[j];
        }
        __syncthreads();
    }

    if (o0 < 64) {          // q/k: fp32 [b][d][n]
#pragma unroll
        for (int i = 0; i < 4; i++) {
            const int o = o0 + ty*4 + i;
            float* dst = (o < 32) ? (g_q + ((size_t)b*OC + o) * N)
                                  : (g_k + ((size_t)b*OC + (o - 32)) * N);
            *reinterpret_cast<float4*>(dst + n0 + tx*4) =
                make_float4(acc[i][0], acc[i][1], acc[i][2], acc[i][3]);
        }
    } else {                // v: bf16 [b][c][n]
#pragma unroll
        for (int i = 0; i < 4; i++) {
            const int c = o0 - 64 + ty*4 + i;
            __nv_bfloat162 lo = __float22bfloat162_rn(make_float2(acc[i][0], acc[i][1]));
            __nv_bfloat162 hi = __float22bfloat162_rn(make_float2(acc[i][2], acc[i][3]));
            *reinterpret_cast<uint2*>(g_v + ((size_t)b*C + c) * N + n0 + tx*4) =
                make_uint2(reinterpret_cast<uint32_t&>(lo), reinterpret_cast<uint32_t&>(hi));
        }
    }
}

// =============================================================================
// K2: S^T tile [j][i] = sum_d k[d][j] q[d][i], fused exp, bf16 store to g_pt.
// =============================================================================
__global__ __launch_bounds__(256)
void k2_scores() {
    const int b  = blockIdx.z;
    const int j0 = blockIdx.y * 128;
    const int i0 = blockIdx.x * 128;
    __shared__ float Ks[32][132];
    __shared__ float Qs[32][132];
    const int t = threadIdx.x, tx = t & 15, ty = t >> 4;

    const float* qb = g_q + (size_t)b * OC * N;
    const float* kb = g_k + (size_t)b * OC * N;
#pragma unroll
    for (int s = 0; s < 4; s++) {
        const int f = t*4 + s*1024, d = f >> 7, mm = f & 127;
        *reinterpret_cast<float4*>(&Ks[d][mm]) =
            *reinterpret_cast<const float4*>(kb + (size_t)d * N + j0 + mm);
        *reinterpret_cast<float4*>(&Qs[d][mm]) =
            *reinterpret_cast<const float4*>(qb + (size_t)d * N + i0 + mm);
    }
    __syncthreads();

    unsigned long long acc[8][4];
#pragma unroll
    for (int r = 0; r < 8; r++)
#pragma unroll
        for (int q = 0; q < 4; q++) acc[r][q] = 0ULL;

#pragma unroll
    for (int d = 0; d < 32; d++) {
        const float4 blo = *reinterpret_cast<const float4*>(&Qs[d][tx*8]);
        const float4 bhi = *reinterpret_cast<const float4*>(&Qs[d][tx*8+4]);
        unsigned long long bb[4] = { pack2(blo.x, blo.y), pack2(blo.z, blo.w),
                                     pack2(bhi.x, bhi.y), pack2(bhi.z, bhi.w) };
        const float4 alo = *reinterpret_cast<const float4*>(&Ks[d][ty*8]);
        const float4 ahi = *reinterpret_cast<const float4*>(&Ks[d][ty*8+4]);
        const float av[8] = { alo.x, alo.y, alo.z, alo.w, ahi.x, ahi.y, ahi.z, ahi.w };
#pragma unroll
        for (int r = 0; r < 8; r++) {
            const unsigned long long a2 = pack2(av[r], av[r]);
#pragma unroll
            for (int q = 0; q < 4; q++) fma2(acc[r][q], a2, bb[q]);
        }
    }

    __nv_bfloat16* pb = g_pt + (size_t)b * N * N;
#pragma unroll
    for (int r = 0; r < 8; r++) {
        const float2 v0 = unpack2(acc[r][0]), v1 = unpack2(acc[r][1]);
        const float2 v2 = unpack2(acc[r][2]), v3 = unpack2(acc[r][3]);
        // |s| < ~15: no max-subtraction needed for fp32 exp
        __nv_bfloat162 h0 = __float22bfloat162_rn(make_float2(__expf(v0.x), __expf(v0.y)));
        __nv_bfloat162 h1 = __float22bfloat162_rn(make_float2(__expf(v1.x), __expf(v1.y)));
        __nv_bfloat162 h2 = __float22bfloat162_rn(make_float2(__expf(v2.x), __expf(v2.y)));
        __nv_bfloat162 h3 = __float22bfloat162_rn(make_float2(__expf(v3.x), __expf(v3.y)));
        uint4 u = make_uint4(reinterpret_cast<uint32_t&>(h0), reinterpret_cast<uint32_t&>(h1),
                             reinterpret_cast<uint32_t&>(h2), reinterpret_cast<uint32_t&>(h3));
        *reinterpret_cast<uint4*>(pb + (size_t)(j0 + ty*8 + r) * N + i0 + tx*8) = u;
    }
}

// =============================================================================
// K3: Z_j = row-sum of bf16 pt[j][:] (deterministic fixed-tree shfl), rz=gamma/Z
// =============================================================================
__global__ __launch_bounds__(256)
void k3_z(const float* __restrict__ gamma) {
    const int b = blockIdx.y;
    const int warp = threadIdx.x >> 5, lane = threadIdx.x & 31;
    const int j = blockIdx.x * 8 + warp;
    const __nv_bfloat16* row = g_pt + ((size_t)b * N + j) * N;
    float s = 0.f;
#pragma unroll
    for (int it = 0; it < 16; it++) {
        uint4 u = *reinterpret_cast<const uint4*>(row + (size_t)(it*32 + lane) * 8);
        const __nv_bfloat162* h = reinterpret_cast<const __nv_bfloat162*>(&u);
#pragma unroll
        for (int q = 0; q < 4; q++) { float2 f = __bfloat1622float2(h[q]); s += f.x + f.y; }
    }
#pragma unroll
    for (int o = 16; o > 0; o >>= 1) s += __shfl_xor_sync(0xffffffffu, s, o);
    if (lane == 0) g_rz[(size_t)b * N + j] = gamma[0] / s;
}

// =============================================================================
// K4: PV GEMM via mma.sync bf16 (HMMA — baseline ISA, works on plain sm_103).
//     Block 128(c) x 128(j), K-chunk 64 over i, 2-stage cp.async pipeline,
//     8 warps (4x2), warp tile 32x64, fused epilogue out = rz*D + x.
// =============================================================================
constexpr int KC4   = 64;                 // K elems per chunk (128 bytes/row)
constexpr int NCH4  = N / KC4;            // 64 chunks
constexpr int T_BY  = 128 * 128;          // 16 KB per tile (128 rows x 128 B)
constexpr int OFF_RZ = 0;                 // 512 B
constexpr int OFF_A0 = 1024;
constexpr int OFF_B0 = OFF_A0 + T_BY;     // 17408
constexpr int OFF_A1 = OFF_B0 + T_BY;     // 33792
constexpr int OFF_B1 = OFF_A1 + T_BY;     // 50176
constexpr int SMEM_K4 = OFF_B1 + T_BY;    // 66560

__device__ __forceinline__ void k4_load(uint32_t sA, uint32_t sB,
        const char* vbase, const char* pbase, int ck) {
    const int t = threadIdx.x;
    const size_t cb = (size_t)ck * (KC4 * 2);          // chunk byte offset in a row
#pragma unroll
    for (int k = 0; k < 4; k++) {                      // A: 128 rows x 8 x 16B
        const int g = t + k * 256, row = g >> 3, gr = g & 7;
        cp16(sA + sw128(row * 128 + gr * 16), vbase + (size_t)row * (N * 2) + cb + gr * 16);
    }
#pragma unroll
    for (int k = 0; k < 4; k++) {                      // B: 128 rows x 8 x 16B
        const int g = t + k * 256, row = g >> 3, gr = g & 7;
        cp16(sB + sw128(row * 128 + gr * 16), pbase + (size_t)row * (N * 2) + cb + gr * 16);
    }
    cp_commit();
}

__global__ __launch_bounds__(256)
void k4_pv(const float* __restrict__ x, float* __restrict__ out) {
    extern __shared__ char smem[];
    const uint32_t sb = smem_u32(smem);
    const int b  = blockIdx.z;
    const int c0 = blockIdx.y * 128;
    const int j0 = blockIdx.x * 128;
    const int t = threadIdx.x, lane = t & 31, wid = t >> 5;
    const int wm = wid & 3, wn = wid >> 2;             // 4x2 warp grid

    if (t < 128) reinterpret_cast<float*>(smem + OFF_RZ)[t] = g_rz[(size_t)b * N + j0 + t];

    const char* vbase = reinterpret_cast<const char*>(g_v  + (size_t)(b * C + c0) * N);
    const char* pbase = reinterpret_cast<const char*>(g_pt + (size_t)b * N * N + (size_t)j0 * N);
    const uint32_t sA[2] = { sb + OFF_A0, sb + OFF_A1 };
    const uint32_t sB[2] = { sb + OFF_B0, sb + OFF_B1 };

    float acc[2][8][4] = {};

    // precomputed ldmatrix lane offsets (byte offsets within a tile, pre-swizzle)
    const uint32_t a_row = wm * 32 + (lane & 15);              // + mi*16
    const uint32_t a_kof = (lane >> 4) * 16;                   // 0 / 16 B
    const uint32_t b_row = wn * 64 + ((lane >> 4) << 3) + (lane & 7);  // + ni2*16
    const uint32_t b_kof = ((lane >> 3) & 1) * 16;             // 0 / 16 B

    k4_load(sA[0], sB[0], vbase, pbase, 0);

    for (int ck = 0; ck < NCH4; ck++) {
        const int s = ck & 1;
        if (ck + 1 < NCH4) { k4_load(sA[s ^ 1], sB[s ^ 1], vbase, pbase, ck + 1); cp_wait<1>(); }
        else               { cp_wait<0>(); }
        __syncthreads();

#pragma unroll
        for (int ks = 0; ks < 4; ks++) {               // 4 x k16 steps
            const uint32_t kb = ks * 32;               // 16 bf16 = 32 B
            uint32_t a[2][4];
#pragma unroll
            for (int mi = 0; mi < 2; mi++)
                ldsm4(a[mi][0], a[mi][1], a[mi][2], a[mi][3],
                      sA[s] + sw128((a_row + mi * 16) * 128 + kb + a_kof));
            uint32_t bfr[4][4];
#pragma unroll
            for (int ni2 = 0; ni2 < 4; ni2++)
                ldsm4(bfr[ni2][0], bfr[ni2][1], bfr[ni2][2], bfr[ni2][3],
                      sB[s] + sw128((b_row + ni2 * 16) * 128 + kb + b_kof));
#pragma unroll
            for (int mi = 0; mi < 2; mi++)
#pragma unroll
                for (int ni2 = 0; ni2 < 4; ni2++) {
                    mma16816(acc[mi][ni2 * 2 + 0], a[mi], &bfr[ni2][0]);
                    mma16816(acc[mi][ni2 * 2 + 1], a[mi], &bfr[ni2][2]);
                }
        }
        __syncthreads();
    }

    // epilogue: out[c][j] = rz[j] * acc + x[c][j]
    const float* rzs = reinterpret_cast<const float*>(smem + OFF_RZ);
    const int qrow = lane >> 2, qcol = 2 * (lane & 3);
#pragma unroll
    for (int mi = 0; mi < 2; mi++) {
        const int c = c0 + wm * 32 + mi * 16 + qrow;
        const float* xr0 = x   + (size_t)(b * C + c) * N + j0;
        float*       or0 = out + (size_t)(b * C + c) * N + j0;
        const float* xr1 = xr0 + 8 * (size_t)N;
        float*       or1 = or0 + 8 * (size_t)N;
#pragma unroll
        for (int ni = 0; ni < 8; ni++) {
            const int col = wn * 64 + ni * 8 + qcol;
            const float rz0 = rzs[col], rz1 = rzs[col + 1];
            const float2 x0 = *reinterpret_cast<const float2*>(xr0 + col);
            const float2 x1 = *reinterpret_cast<const float2*>(xr1 + col);
            float2 o0, o1;
            o0.x = fmaf(acc[mi][ni][0], rz0, x0.x);
            o0.y = fmaf(acc[mi][ni][1], rz1, x0.y);
            o1.x = fmaf(acc[mi][ni][2], rz0, x1.x);
            o1.y = fmaf(acc[mi][ni][3], rz1, x1.y);
            *reinterpret_cast<float2*>(or0 + col) = o0;
            *reinterpret_cast<float2*>(or1 + col) = o1;
        }
    }
}

// =============================================================================
extern "C" void kernel_launch(void* const* d_in, const int* in_sizes, int n_in,
                              void* d_out, int out_size) {
    const float* x     = (const float*)d_in[0];
    const float* Wf    = (const float*)d_in[1];
    const float* Wg    = (const float*)d_in[2];
    const float* Wh    = (const float*)d_in[3];
    const float* gamma = (const float*)d_in[4];
    float* out = (float*)d_out;

    cudaFuncSetAttribute(k4_pv, cudaFuncAttributeMaxDynamicSharedMemorySize, SMEM_K4);

    k1_qkv   <<<dim3(N / 64, 320 / 64, B), 256>>>(x, Wf, Wg, Wh);
    k2_scores<<<dim3(N / 128, N / 128, B), 256>>>();
    k3_z     <<<dim3(N / 8, B),            256>>>(gamma);
    k4_pv    <<<dim3(N / 128, C / 128, B), 256, SMEM_K4>>>(x, out);
}